// round 17
// baseline (speedup 1.0000x reference)
#include <cuda_runtime.h>
#include <cuda_fp16.h>

#define NE   100000
#define NN   16384
#define NM   32
#define NR   64
#define WPAD 20      // 16B-aligned W rows

#define R_WORDS (NR * 128)   // fp16 R table: 64 rel x 256 halves

__device__ __half2 g_ent[NE * 8];

__global__ void k_cvt(const float2* __restrict__ ent2) {
    int i = blockIdx.x * blockDim.x + threadIdx.x;
    if (i < NE * 8) {
        float2 v = __ldg(ent2 + i);
        g_ent[i] = __floats2half2_rn(v.x, v.y);
    }
}

static __device__ __forceinline__ __half2 h2c(unsigned int u) {
    return *reinterpret_cast<__half2*>(&u);
}

__global__ __launch_bounds__(256, 4)
void ripple_kernel(const int*   __restrict__ nodes,
                   const int*   __restrict__ mh,
                   const int*   __restrict__ mr,
                   const int*   __restrict__ mt,
                   const float* __restrict__ ent,
                   const float* __restrict__ rel,
                   const float* __restrict__ W,
                   float*       __restrict__ out)
{
    extern __shared__ unsigned int shm[];
    float* shW = reinterpret_cast<float*>(shm + R_WORDS);

    // Stage R as fp16 (identity layout: half index = rid*256 + d*16 + e)
    {
        const float4* rel4 = reinterpret_cast<const float4*>(rel);
        for (int i = threadIdx.x; i < NR * 64; i += blockDim.x) {
            float4 v = rel4[i];
            __half2 a = __floats2half2_rn(v.x, v.y);
            __half2 b = __floats2half2_rn(v.z, v.w);
            shm[2*i]   = *reinterpret_cast<unsigned int*>(&a);
            shm[2*i+1] = *reinterpret_cast<unsigned int*>(&b);
        }
    }
    for (int i = threadIdx.x; i < 256; i += blockDim.x)
        shW[(i >> 4) * WPAD + (i & 15)] = W[i];
    __syncthreads();

    const unsigned F = 0xffffffffu;
    const int lane  = threadIdx.x & 31;
    const int gw    = (blockIdx.x * blockDim.x + threadIdx.x) >> 5;
    const int nw    = (gridDim.x * blockDim.x) >> 5;
    const int g     = lane >> 3;        // octet id (0..3)
    const int k     = lane & 7;         // position within octet
    const int kh    = k & 1;            // e-half of h for scores
    const int kc    = k & 3;            // t chunk accumulated
    const int khalf = k >> 2;           // r-range half (0/1)
    const int k2    = (k >> 1) & 3;     // d-offset selector
    const int myd   = lane & 15;

    const float4* ent4  = reinterpret_cast<const float4*>(ent);
    const uint4*  shR4  = reinterpret_cast<const uint4*>(shm);
    const uint4*  entH4 = reinterpret_cast<const uint4*>(g_ent);
    const uint2*  entH2 = reinterpret_cast<const uint2*>(g_ent);

    for (int n = gw; n < NN; n += nw) {
        // item row pointer (uniform, L1/L2-hot); keep only the 4 score elements
        const float4* itrow = ent4 + (size_t)__ldg(nodes + n) * 4;
        float itp[4];
        #pragma unroll
        for (int j = 0; j < 4; j++) {
            float4 v = __ldg(itrow + j);
            itp[j] = (k2 == 0) ? v.x : (k2 == 1) ? v.y : (k2 == 2) ? v.z : v.w;
        }

        float res = 0.f;

        #pragma unroll
        for (int hop = 0; hop < 2; hop++) {
            const int sbase = (hop * NN + n) * NM;

            // ---- coalesced index preload: one lane = one slot ----
            const int my_h = __ldg(mh + sbase + lane);
            const int my_r = __ldg(mr + sbase + lane);
            const int my_t = __ldg(mt + sbase + lane);

            // ---- score partials: a[r] = this lane's partial for slot 4r+g ----
            float a[8];
            #pragma unroll
            for (int r = 0; r < 8; r++) {
                const int src = 4 * r + g;
                const int hid = __shfl_sync(F, my_h, src);
                const int rid = __shfl_sync(F, my_r, src);
                uint4 hw = __ldg(entH4 + (size_t)hid * 2 + kh);
                __half2 h0 = h2c(hw.x), h1 = h2c(hw.y), h2v = h2c(hw.z), h3 = h2c(hw.w);

                const uint4* rb = shR4 + rid * 32 + k;       // conflict-free
                float sp = 0.f;
                #pragma unroll
                for (int j = 0; j < 4; j++) {                // d = 4j + k2
                    uint4 w = rb[8 * j];
                    __half2 acc = __hmul2(h2c(w.x), h0);
                    acc = __hfma2(h2c(w.y), h1, acc);
                    acc = __hfma2(h2c(w.z), h2v, acc);
                    acc = __hfma2(h2c(w.w), h3, acc);
                    float2 f = __half22float2(acc);
                    sp = fmaf(itp[j], f.x + f.y, sp);
                }
                a[r] = sp;
            }

            // ---- octet vector butterfly (7 shfl): lane 8g+k gets score of slot 4k+g ----
            float s;
            {
                float c[4];
                #pragma unroll
                for (int j = 0; j < 4; j++) {
                    float sent = khalf ? a[j] : a[j + 4];
                    float recv = __shfl_xor_sync(F, sent, 4);
                    c[j] = (khalf ? a[j + 4] : a[j]) + recv;
                }
                const int b1 = (k >> 1) & 1;
                float d0, d1;
                {
                    float sent = b1 ? c[0] : c[2];
                    float recv = __shfl_xor_sync(F, sent, 2);
                    d0 = (b1 ? c[2] : c[0]) + recv;
                }
                {
                    float sent = b1 ? c[1] : c[3];
                    float recv = __shfl_xor_sync(F, sent, 2);
                    d1 = (b1 ? c[3] : c[1]) + recv;
                }
                const int b0 = k & 1;
                float sent = b0 ? d0 : d1;
                float recv = __shfl_xor_sync(F, sent, 1);
                s = (b0 ? d1 : d0) + recv;
            }

            // ---- softmax (no max-subtraction: |s| is O(0.3), exp is safe) ----
            float ev = __expf(s);
            float sum = ev;
            #pragma unroll
            for (int st = 1; st <= 16; st <<= 1)
                sum += __shfl_xor_sync(F, sum, st);
            float pown = __fdividef(ev, sum);      // p of slot 4k+g

            // weights for this lane's tail slots (slot 4r'+g lives on lane 8g+r')
            float pw[4];
            #pragma unroll
            for (int rr = 0; rr < 4; rr++)
                pw[rr] = __shfl_sync(F, pown, (lane & 24) + 4 * khalf + rr);

            // ---- o = sum p_m * t_m (fp16 t chunks, fp32 accumulate) ----
            float ox = 0.f, oy = 0.f, oz = 0.f, ow = 0.f;
            #pragma unroll
            for (int rr = 0; rr < 4; rr++) {
                const int r   = 4 * khalf + rr;
                const int tid = __shfl_sync(F, my_t, 4 * r + g);
                uint2 tw = __ldg(entH2 + (size_t)tid * 4 + kc);
                float2 ta = __half22float2(h2c(tw.x));
                float2 tb = __half22float2(h2c(tw.y));
                ox = fmaf(pw[rr], ta.x, ox); oy = fmaf(pw[rr], ta.y, oy);
                oz = fmaf(pw[rr], tb.x, oz); ow = fmaf(pw[rr], tb.y, ow);
            }
            #pragma unroll
            for (int st = 4; st <= 16; st <<= 1) {
                ox += __shfl_xor_sync(F, ox, st);
                oy += __shfl_xor_sync(F, oy, st);
                oz += __shfl_xor_sync(F, oz, st);
                ow += __shfl_xor_sync(F, ow, st);
            }
            // lane cc holds fully-reduced o chunk cc

            if (hop == 0) {
                float nd = 0.f, omyd = 0.f;
                const float* wr = shW + myd * WPAD;
                const int mycc = myd >> 2, mycomp = myd & 3;
                #pragma unroll
                for (int cc = 0; cc < 4; cc++) {
                    float o0 = __shfl_sync(F, ox, cc);
                    float o1 = __shfl_sync(F, oy, cc);
                    float o2 = __shfl_sync(F, oz, cc);
                    float o3 = __shfl_sync(F, ow, cc);
                    float4 iv = __ldg(itrow + cc);
                    float4 wv = *reinterpret_cast<const float4*>(wr + 4 * cc);
                    nd = fmaf(iv.x + o0, wv.x, nd);
                    nd = fmaf(iv.y + o1, wv.y, nd);
                    nd = fmaf(iv.z + o2, wv.z, nd);
                    nd = fmaf(iv.w + o3, wv.w, nd);
                    if (cc == mycc)
                        omyd = (mycomp == 0) ? o0 : (mycomp == 1) ? o1
                             : (mycomp == 2) ? o2 : o3;
                }
                res = 2.f * omyd;
                // itp for hop 1 from the updated item (nd on lanes 0..15)
                #pragma unroll
                for (int j = 0; j < 4; j++)
                    itp[j] = __shfl_sync(F, nd, 4 * j + k2);
            } else {
                const int src = myd >> 2;
                float t0 = __shfl_sync(F, ox, src);
                float t1 = __shfl_sync(F, oy, src);
                float t2 = __shfl_sync(F, oz, src);
                float t3 = __shfl_sync(F, ow, src);
                const int comp = myd & 3;
                res += (comp == 0) ? t0 : (comp == 1) ? t1 : (comp == 2) ? t2 : t3;
            }
        }

        if (lane < 16) out[n * 16 + lane] = res;
    }
}

extern "C" void kernel_launch(void* const* d_in, const int* in_sizes, int n_in,
                              void* d_out, int out_size)
{
    const int*   nodes = (const int*)  d_in[0];
    const int*   mh    = (const int*)  d_in[1];
    const int*   mr    = (const int*)  d_in[2];
    const int*   mt    = (const int*)  d_in[3];
    const float* ent   = (const float*)d_in[4];
    const float* rel   = (const float*)d_in[5];
    const float* W     = (const float*)d_in[6];
    float*       out   = (float*)      d_out;

    k_cvt<<<(NE * 8 + 255) / 256, 256>>>(reinterpret_cast<const float2*>(ent));

    const int smem = R_WORDS * 4 + 16 * WPAD * 4;   // 32768 + 1280 B
    cudaFuncSetAttribute(ripple_kernel, cudaFuncAttributeMaxDynamicSharedMemorySize, smem);

    ripple_kernel<<<148 * 4, 256, smem>>>(nodes, mh, mr, mt, ent, rel, W, out);
}